// round 1
// baseline (speedup 1.0000x reference)
#include <cuda_runtime.h>
#include <cuda_bf16.h>

#define NUM_TAGS 9
#define DDIM 64
#define HID 768
#define SEQ 512
#define BATCH 16
#define NQK (NUM_TAGS * 2 * DDIM)   /* 1152 */
#define MASKV 1e12f

// Scratch: RoPE'd Q and K in bf16, layout [b][tag][s][d]
__device__ __nv_bfloat16 g_Q[(size_t)BATCH * NUM_TAGS * SEQ * DDIM];
__device__ __nv_bfloat16 g_K[(size_t)BATCH * NUM_TAGS * SEQ * DDIM];

__device__ __forceinline__ void mma16816(float* c, const unsigned* a, const unsigned* b) {
    asm volatile(
        "mma.sync.aligned.m16n8k16.row.col.f32.bf16.bf16.f32 "
        "{%0,%1,%2,%3}, {%4,%5,%6,%7}, {%8,%9}, {%0,%1,%2,%3};\n"
        : "+f"(c[0]), "+f"(c[1]), "+f"(c[2]), "+f"(c[3])
        : "r"(a[0]), "r"(a[1]), "r"(a[2]), "r"(a[3]), "r"(b[0]), "r"(b[1]));
}

// ===================== Kernel A: GEMM1 + bias + RoPE =====================
// out(8192 x 1152) = enc(8192 x 768) @ W(768 x 1152) + b, then RoPE per tag,
// split into Q (first 64 cols of each 128-col tag block) and K (last 64).
// CTA tile: 128(M) x 128(N, one tag). 8 warps as 4(M) x 2(N); warp = 32x64.
__global__ __launch_bounds__(256) void gemm1_rope(
    const float* __restrict__ enc, const float* __restrict__ W,
    const float* __restrict__ bias)
{
    const int bm  = blockIdx.x;        // 0..63
    const int tag = blockIdx.y;        // 0..8
    const int tid  = threadIdx.x;
    const int lane = tid & 31, wid = tid >> 5;
    const int wm = wid & 3, wn = wid >> 1 & 0; // placeholder fix below
    const int warp_m = wid & 3;        // 0..3
    const int warp_n = wid >> 2;       // 0..1
    const int g  = lane >> 2;          // groupID 0..7
    const int t4 = lane & 3;           // threadID in group
    (void)wm; (void)wn;

    __shared__ __align__(16) __nv_bfloat16 As[128][40];   // M x K, pad 8
    __shared__ __align__(16) __nv_bfloat16 Bs[32][136];   // K x N, pad 8

    const int m0 = bm * 128;
    const int n0 = tag * 128;

    float acc[2][8][4];
    #pragma unroll
    for (int mi = 0; mi < 2; ++mi)
        #pragma unroll
        for (int ni = 0; ni < 8; ++ni)
            #pragma unroll
            for (int q = 0; q < 4; ++q) acc[mi][ni][q] = 0.f;

    for (int kt = 0; kt < HID / 32; ++kt) {
        const int k0 = kt * 32;
        __syncthreads();   // protect smem from previous iteration's readers
        #pragma unroll
        for (int it = 0; it < 4; ++it) {
            int idx = tid + it * 256;
            // A: 128 rows x 8 float4
            {
                int r = idx >> 3, c = (idx & 7) * 4;
                float4 v = *(const float4*)(enc + (size_t)(m0 + r) * HID + k0 + c);
                *(__nv_bfloat162*)&As[r][c]     = __floats2bfloat162_rn(v.x, v.y);
                *(__nv_bfloat162*)&As[r][c + 2] = __floats2bfloat162_rn(v.z, v.w);
            }
            // B: 32 k-rows x 32 float4 (keep K-major layout, coalesced)
            {
                int kr = idx >> 5, cn = (idx & 31) * 4;
                float4 v = *(const float4*)(W + (size_t)(k0 + kr) * NQK + n0 + cn);
                *(__nv_bfloat162*)&Bs[kr][cn]     = __floats2bfloat162_rn(v.x, v.y);
                *(__nv_bfloat162*)&Bs[kr][cn + 2] = __floats2bfloat162_rn(v.z, v.w);
            }
        }
        __syncthreads();

        #pragma unroll
        for (int kk = 0; kk < 32; kk += 16) {
            unsigned a[2][4], bf[8][2];
            #pragma unroll
            for (int mi = 0; mi < 2; ++mi) {
                int r = warp_m * 32 + mi * 16 + g;
                a[mi][0] = *(const unsigned*)&As[r][kk + t4 * 2];
                a[mi][1] = *(const unsigned*)&As[r + 8][kk + t4 * 2];
                a[mi][2] = *(const unsigned*)&As[r][kk + t4 * 2 + 8];
                a[mi][3] = *(const unsigned*)&As[r + 8][kk + t4 * 2 + 8];
            }
            #pragma unroll
            for (int ni = 0; ni < 8; ++ni) {
                int n = warp_n * 64 + ni * 8 + g;
                unsigned lo0 = __bfloat16_as_ushort(Bs[kk + t4 * 2][n]);
                unsigned hi0 = __bfloat16_as_ushort(Bs[kk + t4 * 2 + 1][n]);
                unsigned lo1 = __bfloat16_as_ushort(Bs[kk + t4 * 2 + 8][n]);
                unsigned hi1 = __bfloat16_as_ushort(Bs[kk + t4 * 2 + 9][n]);
                bf[ni][0] = lo0 | (hi0 << 16);
                bf[ni][1] = lo1 | (hi1 << 16);
            }
            #pragma unroll
            for (int mi = 0; mi < 2; ++mi)
                #pragma unroll
                for (int ni = 0; ni < 8; ++ni)
                    mma16816(acc[mi][ni], a[mi], bf[ni]);
        }
    }

    // Epilogue: bias + RoPE, write bf16 Q/K
    const float LN1E4_OVER_32 = 0.28782313662425572f;  // ln(10000)/32
    #pragma unroll
    for (int ni = 0; ni < 8; ++ni) {
        int col = warp_n * 64 + ni * 8 + t4 * 2;   // 0..127 within tag block
        bool isq = col < 64;
        int dcol = col & 63;
        float inv = expf(-(float)(dcol >> 1) * LN1E4_OVER_32);
        float b0 = bias[n0 + col];
        float b1 = bias[n0 + col + 1];
        __nv_bfloat16* dstbase = isq ? g_Q : g_K;
        #pragma unroll
        for (int mi = 0; mi < 2; ++mi) {
            #pragma unroll
            for (int rr = 0; rr < 2; ++rr) {
                int m = m0 + warp_m * 32 + mi * 16 + g + rr * 8;
                int bb = m >> 9, s = m & 511;
                float sv, cv;
                sincosf((float)s * inv, &sv, &cv);
                float v0 = acc[mi][ni][rr * 2 + 0] + b0;
                float v1 = acc[mi][ni][rr * 2 + 1] + b1;
                float y0 = v0 * cv - v1 * sv;
                float y1 = v1 * cv + v0 * sv;
                size_t off = (((size_t)(bb * NUM_TAGS + tag) * SEQ + s) * DDIM + dcol);
                *(__nv_bfloat162*)(dstbase + off) = __floats2bfloat162_rn(y0, y1);
            }
        }
    }
}

// ===================== Kernel B: QK^T + mask + scale =====================
// Per (b,h): logits(512x512) = Q(512x64) @ K^T, then pad/causal mask, /8.
// CTA tile 128(s) x 128(t), full K=64 resident. Tiles fully below the
// diagonal skip the GEMM (logit term is 1e-12 relative to the mask value).
__global__ __launch_bounds__(256) void gemm2_mask(
    const int* __restrict__ amask, float* __restrict__ out)
{
    const int tt = blockIdx.x;         // t tile 0..3
    const int st = blockIdx.y;         // s tile 0..3
    const int bh = blockIdx.z;         // 0..143 = b*9+h
    const int bidx = bh / NUM_TAGS;
    const int t0 = tt * 128, s0 = st * 128;
    const int tid = threadIdx.x;

    float* outrow0 = out + ((size_t)bh * SEQ + s0) * SEQ;

    if (t0 < s0) {
        // fully causal-masked tile: value = ((p-2) * 1e12)/8, logit negligible
        #pragma unroll
        for (int it = 0; it < 16; ++it) {
            int idx = tid + it * 256;          // 128 rows x 32 quad-cols
            int r = idx >> 5, c4 = (idx & 31) * 4;
            int4 mv = *(const int4*)(amask + bidx * SEQ + t0 + c4);
            float4 o;
            o.x = ((float)mv.x - 2.0f) * 1.25e11f;
            o.y = ((float)mv.y - 2.0f) * 1.25e11f;
            o.z = ((float)mv.z - 2.0f) * 1.25e11f;
            o.w = ((float)mv.w - 2.0f) * 1.25e11f;
            *(float4*)(outrow0 + (size_t)r * SEQ + t0 + c4) = o;
        }
        return;
    }

    __shared__ __align__(16) __nv_bfloat16 Qs[128][72];
    __shared__ __align__(16) __nv_bfloat16 Ks[128][72];

    const __nv_bfloat16* Qg = g_Q + ((size_t)bh * SEQ + s0) * DDIM;
    const __nv_bfloat16* Kg = g_K + ((size_t)bh * SEQ + t0) * DDIM;
    #pragma unroll
    for (int it = 0; it < 4; ++it) {
        int idx = tid + it * 256;
        int r = idx >> 3, c8 = (idx & 7) * 8;
        *(uint4*)&Qs[r][c8] = *(const uint4*)(Qg + (size_t)r * DDIM + c8);
        *(uint4*)&Ks[r][c8] = *(const uint4*)(Kg + (size_t)r * DDIM + c8);
    }
    __syncthreads();

    const int lane = tid & 31, wid = tid >> 5;
    const int warp_m = wid & 3, warp_n = wid >> 2;
    const int g = lane >> 2, t4 = lane & 3;

    float acc[2][8][4];
    #pragma unroll
    for (int mi = 0; mi < 2; ++mi)
        #pragma unroll
        for (int ni = 0; ni < 8; ++ni)
            #pragma unroll
            for (int q = 0; q < 4; ++q) acc[mi][ni][q] = 0.f;

    #pragma unroll
    for (int kk = 0; kk < 64; kk += 16) {
        unsigned a[2][4], bf[8][2];
        #pragma unroll
        for (int mi = 0; mi < 2; ++mi) {
            int r = warp_m * 32 + mi * 16 + g;
            a[mi][0] = *(const unsigned*)&Qs[r][kk + t4 * 2];
            a[mi][1] = *(const unsigned*)&Qs[r + 8][kk + t4 * 2];
            a[mi][2] = *(const unsigned*)&Qs[r][kk + t4 * 2 + 8];
            a[mi][3] = *(const unsigned*)&Qs[r + 8][kk + t4 * 2 + 8];
        }
        #pragma unroll
        for (int ni = 0; ni < 8; ++ni) {
            int n = warp_n * 64 + ni * 8 + g;
            bf[ni][0] = *(const unsigned*)&Ks[n][kk + t4 * 2];
            bf[ni][1] = *(const unsigned*)&Ks[n][kk + t4 * 2 + 8];
        }
        #pragma unroll
        for (int mi = 0; mi < 2; ++mi)
            #pragma unroll
            for (int ni = 0; ni < 8; ++ni)
                mma16816(acc[mi][ni], a[mi], bf[ni]);
    }

    // Epilogue: pad mask (per t), causal mask (t < s), scale 1/8
    #pragma unroll
    for (int ni = 0; ni < 8; ++ni) {
        int col = t0 + warp_n * 64 + ni * 8 + t4 * 2;   // global t
        float p0 = (float)amask[bidx * SEQ + col];
        float p1 = (float)amask[bidx * SEQ + col + 1];
        float pm0 = (1.0f - p0) * MASKV;
        float pm1 = (1.0f - p1) * MASKV;
        #pragma unroll
        for (int mi = 0; mi < 2; ++mi) {
            #pragma unroll
            for (int rr = 0; rr < 2; ++rr) {
                int row = s0 + warp_m * 32 + mi * 16 + g + rr * 8;  // global s
                float v0 = acc[mi][ni][rr * 2 + 0] * p0 - pm0 - ((col     < row) ? MASKV : 0.f);
                float v1 = acc[mi][ni][rr * 2 + 1] * p1 - pm1 - ((col + 1 < row) ? MASKV : 0.f);
                float2 o;
                o.x = v0 * 0.125f;
                o.y = v1 * 0.125f;
                *(float2*)(out + ((size_t)bh * SEQ + row) * SEQ + col) = o;
            }
        }
    }
}

extern "C" void kernel_launch(void* const* d_in, const int* in_sizes, int n_in,
                              void* d_out, int out_size) {
    (void)in_sizes; (void)n_in; (void)out_size;
    const float* enc  = (const float*)d_in[0];
    // d_in[1] = token_ids (int64) — unused by the reference computation
    const int*   am   = (const int*)d_in[2];
    const float* W    = (const float*)d_in[3];
    const float* bias = (const float*)d_in[4];
    float* out = (float*)d_out;

    dim3 g1(64, NUM_TAGS);
    gemm1_rope<<<g1, 256>>>(enc, W, bias);

    dim3 g2(4, 4, BATCH * NUM_TAGS);
    gemm2_mask<<<g2, 256>>>(am, out);
}

// round 2
// speedup vs baseline: 1.1461x; 1.1461x over previous
#include <cuda_runtime.h>
#include <cuda_bf16.h>

#define NUM_TAGS 9
#define DDIM 64
#define HID 768
#define SEQ 512
#define BATCH 16
#define NQK (NUM_TAGS * 2 * DDIM)   /* 1152 */
#define MASKV 1e12f

// Scratch
__device__ __nv_bfloat16 g_Q[(size_t)BATCH * NUM_TAGS * SEQ * DDIM];
__device__ __nv_bfloat16 g_K[(size_t)BATCH * NUM_TAGS * SEQ * DDIM];
__device__ __nv_bfloat16 g_encb[(size_t)BATCH * SEQ * HID];      // enc in bf16
__device__ __nv_bfloat16 g_Wt[(size_t)NQK * HID];                // W^T bf16 [n][k]

__device__ __forceinline__ void mma16816(float* c, const unsigned* a, const unsigned* b) {
    asm volatile(
        "mma.sync.aligned.m16n8k16.row.col.f32.bf16.bf16.f32 "
        "{%0,%1,%2,%3}, {%4,%5,%6,%7}, {%8,%9}, {%0,%1,%2,%3};\n"
        : "+f"(c[0]), "+f"(c[1]), "+f"(c[2]), "+f"(c[3])
        : "r"(a[0]), "r"(a[1]), "r"(a[2]), "r"(a[3]), "r"(b[0]), "r"(b[1]));
}

__device__ __forceinline__ void cpasync16(void* s, const void* g) {
    unsigned sa = (unsigned)__cvta_generic_to_shared(s);
    asm volatile("cp.async.cg.shared.global [%0], [%1], 16;\n" :: "r"(sa), "l"(g));
}
#define CP_COMMIT() asm volatile("cp.async.commit_group;\n")

// ===================== Prep: enc fp32 -> bf16 =====================
__global__ __launch_bounds__(256) void prep_enc(const float* __restrict__ enc,
                                                __nv_bfloat16* __restrict__ dst) {
    const int NV = BATCH * SEQ * HID / 4;            // float4 count
    const int stride = gridDim.x * blockDim.x;
    for (int i = blockIdx.x * blockDim.x + threadIdx.x; i < NV; i += stride) {
        float4 v = *(const float4*)(enc + (size_t)i * 4);
        __nv_bfloat162 lo = __floats2bfloat162_rn(v.x, v.y);
        __nv_bfloat162 hi = __floats2bfloat162_rn(v.z, v.w);
        uint2 o = { *(unsigned*)&lo, *(unsigned*)&hi };
        *(uint2*)(dst + (size_t)i * 4) = o;
    }
}

// ===================== Prep: W fp32 [k][n] -> bf16 Wt [n][k] =====================
__global__ __launch_bounds__(256) void prep_w(const float* __restrict__ W,
                                              __nv_bfloat16* __restrict__ Wt) {
    __shared__ __nv_bfloat16 t[64][72];
    const int kb = blockIdx.x * 64, nb = blockIdx.y * 64;
    const int tid = threadIdx.x;
    #pragma unroll
    for (int it = 0; it < 4; ++it) {
        int idx = tid + it * 256;                    // 64 rows x 16 float4
        int r = idx >> 4, c4 = (idx & 15) * 4;
        float4 v = *(const float4*)(W + (size_t)(kb + r) * NQK + nb + c4);
        t[c4 + 0][r] = __float2bfloat16_rn(v.x);
        t[c4 + 1][r] = __float2bfloat16_rn(v.y);
        t[c4 + 2][r] = __float2bfloat16_rn(v.z);
        t[c4 + 3][r] = __float2bfloat16_rn(v.w);
    }
    __syncthreads();
    #pragma unroll
    for (int it = 0; it < 4; ++it) {
        int idx = tid + it * 256;                    // 64 rows(n) x 16 uint2
        int r = idx >> 4, c4 = (idx & 15) * 4;
        *(uint2*)(Wt + (size_t)(nb + r) * HID + kb + c4) = *(uint2*)&t[r][c4];
    }
}

// ===================== Kernel A: GEMM1 + bias + RoPE =====================
// out(8192 x 1152) = encb @ Wt^T + b, RoPE per tag, split Q/K.
// CTA tile 128(M) x 128(N=one tag); cp.async double-buffered, K-tile 32.
__global__ __launch_bounds__(256) void gemm1_rope(
    const float* __restrict__ bias)
{
    const int bm  = blockIdx.x;        // 0..63
    const int tag = blockIdx.y;        // 0..8
    const int tid  = threadIdx.x;
    const int lane = tid & 31, wid = tid >> 5;
    const int warp_m = wid & 3;        // 0..3
    const int warp_n = wid >> 2;       // 0..1
    const int g  = lane >> 2;
    const int t4 = lane & 3;

    __shared__ __align__(16) __nv_bfloat16 As[2][128][40];   // M x K(32), pad 8
    __shared__ __align__(16) __nv_bfloat16 Bs[2][128][40];   // N x K(32), pad 8

    const int m0 = bm * 128;
    const int n0 = tag * 128;
    const __nv_bfloat16* Ag = g_encb + (size_t)m0 * HID;
    const __nv_bfloat16* Bg = g_Wt   + (size_t)n0 * HID;

    float acc[2][8][4];
    #pragma unroll
    for (int mi = 0; mi < 2; ++mi)
        #pragma unroll
        for (int ni = 0; ni < 8; ++ni)
            #pragma unroll
            for (int q = 0; q < 4; ++q) acc[mi][ni][q] = 0.f;

    const int NT = HID / 32;           // 24

    // issue loads for k-tile kt into buffer buf
    auto issue = [&](int kt, int buf) {
        const int k0 = kt * 32;
        #pragma unroll
        for (int it = 0; it < 2; ++it) {
            int idx = tid + it * 256;                // 128 rows x 4 chunks(16B)
            int r = idx >> 2, c8 = (idx & 3) * 8;
            cpasync16(&As[buf][r][c8], Ag + (size_t)r * HID + k0 + c8);
        }
        #pragma unroll
        for (int it = 0; it < 2; ++it) {
            int idx = tid + it * 256;
            int r = idx >> 2, c8 = (idx & 3) * 8;
            cpasync16(&Bs[buf][r][c8], Bg + (size_t)r * HID + k0 + c8);
        }
    };

    issue(0, 0); CP_COMMIT();

    for (int kt = 0; kt < NT; ++kt) {
        const int buf = kt & 1;
        if (kt + 1 < NT) {
            issue(kt + 1, buf ^ 1); CP_COMMIT();
            asm volatile("cp.async.wait_group 1;\n");
        } else {
            asm volatile("cp.async.wait_group 0;\n");
        }
        __syncthreads();

        #pragma unroll
        for (int kk = 0; kk < 32; kk += 16) {
            unsigned a[2][4], bf[8][2];
            #pragma unroll
            for (int mi = 0; mi < 2; ++mi) {
                int r = warp_m * 32 + mi * 16 + g;
                a[mi][0] = *(const unsigned*)&As[buf][r][kk + t4 * 2];
                a[mi][1] = *(const unsigned*)&As[buf][r + 8][kk + t4 * 2];
                a[mi][2] = *(const unsigned*)&As[buf][r][kk + t4 * 2 + 8];
                a[mi][3] = *(const unsigned*)&As[buf][r + 8][kk + t4 * 2 + 8];
            }
            #pragma unroll
            for (int ni = 0; ni < 8; ++ni) {
                int n = warp_n * 64 + ni * 8 + g;
                bf[ni][0] = *(const unsigned*)&Bs[buf][n][kk + t4 * 2];
                bf[ni][1] = *(const unsigned*)&Bs[buf][n][kk + t4 * 2 + 8];
            }
            #pragma unroll
            for (int mi = 0; mi < 2; ++mi)
                #pragma unroll
                for (int ni = 0; ni < 8; ++ni)
                    mma16816(acc[mi][ni], a[mi], bf[ni]);
        }
        __syncthreads();
    }

    // Epilogue: bias + RoPE, write bf16 Q/K
    const float LN1E4_OVER_32 = 0.28782313662425572f;  // ln(10000)/32
    #pragma unroll
    for (int ni = 0; ni < 8; ++ni) {
        int col = warp_n * 64 + ni * 8 + t4 * 2;        // 0..127 within tag
        bool isq = col < 64;
        int dcol = col & 63;
        float inv = expf(-(float)(dcol >> 1) * LN1E4_OVER_32);
        float b0 = bias[n0 + col];
        float b1 = bias[n0 + col + 1];
        __nv_bfloat16* dstbase = isq ? g_Q : g_K;
        #pragma unroll
        for (int mi = 0; mi < 2; ++mi) {
            #pragma unroll
            for (int rr = 0; rr < 2; ++rr) {
                int m = m0 + warp_m * 32 + mi * 16 + g + rr * 8;
                int bb = m >> 9, s = m & 511;
                float sv, cv;
                sincosf((float)s * inv, &sv, &cv);
                float v0 = acc[mi][ni][rr * 2 + 0] + b0;
                float v1 = acc[mi][ni][rr * 2 + 1] + b1;
                float y0 = v0 * cv - v1 * sv;
                float y1 = v1 * cv + v0 * sv;
                size_t off = (((size_t)(bb * NUM_TAGS + tag) * SEQ + s) * DDIM + dcol);
                *(__nv_bfloat162*)(dstbase + off) = __floats2bfloat162_rn(y0, y1);
            }
        }
    }
}

// ===================== Kernel B: QK^T + mask + scale =====================
__global__ __launch_bounds__(256) void gemm2_mask(
    const int* __restrict__ amask, float* __restrict__ out)
{
    const int tt = blockIdx.x;
    const int st = blockIdx.y;
    const int bh = blockIdx.z;
    const int bidx = bh / NUM_TAGS;
    const int t0 = tt * 128, s0 = st * 128;
    const int tid = threadIdx.x;

    float* outrow0 = out + ((size_t)bh * SEQ + s0) * SEQ;

    if (t0 < s0) {
        #pragma unroll
        for (int it = 0; it < 16; ++it) {
            int idx = tid + it * 256;
            int r = idx >> 5, c4 = (idx & 31) * 4;
            int4 mv = *(const int4*)(amask + bidx * SEQ + t0 + c4);
            float4 o;
            o.x = ((float)mv.x - 2.0f) * 1.25e11f;
            o.y = ((float)mv.y - 2.0f) * 1.25e11f;
            o.z = ((float)mv.z - 2.0f) * 1.25e11f;
            o.w = ((float)mv.w - 2.0f) * 1.25e11f;
            *(float4*)(outrow0 + (size_t)r * SEQ + t0 + c4) = o;
        }
        return;
    }

    __shared__ __align__(16) __nv_bfloat16 Qs[128][72];
    __shared__ __align__(16) __nv_bfloat16 Ks[128][72];

    const __nv_bfloat16* Qg = g_Q + ((size_t)bh * SEQ + s0) * DDIM;
    const __nv_bfloat16* Kg = g_K + ((size_t)bh * SEQ + t0) * DDIM;
    #pragma unroll
    for (int it = 0; it < 4; ++it) {
        int idx = tid + it * 256;
        int r = idx >> 3, c8 = (idx & 7) * 8;
        *(uint4*)&Qs[r][c8] = *(const uint4*)(Qg + (size_t)r * DDIM + c8);
        *(uint4*)&Ks[r][c8] = *(const uint4*)(Kg + (size_t)r * DDIM + c8);
    }
    __syncthreads();

    const int lane = tid & 31, wid = tid >> 5;
    const int warp_m = wid & 3, warp_n = wid >> 2;
    const int g = lane >> 2, t4 = lane & 3;

    float acc[2][8][4];
    #pragma unroll
    for (int mi = 0; mi < 2; ++mi)
        #pragma unroll
        for (int ni = 0; ni < 8; ++ni)
            #pragma unroll
            for (int q = 0; q < 4; ++q) acc[mi][ni][q] = 0.f;

    #pragma unroll
    for (int kk = 0; kk < 64; kk += 16) {
        unsigned a[2][4], bf[8][2];
        #pragma unroll
        for (int mi = 0; mi < 2; ++mi) {
            int r = warp_m * 32 + mi * 16 + g;
            a[mi][0] = *(const unsigned*)&Qs[r][kk + t4 * 2];
            a[mi][1] = *(const unsigned*)&Qs[r + 8][kk + t4 * 2];
            a[mi][2] = *(const unsigned*)&Qs[r][kk + t4 * 2 + 8];
            a[mi][3] = *(const unsigned*)&Qs[r + 8][kk + t4 * 2 + 8];
        }
        #pragma unroll
        for (int ni = 0; ni < 8; ++ni) {
            int n = warp_n * 64 + ni * 8 + g;
            bf[ni][0] = *(const unsigned*)&Ks[n][kk + t4 * 2];
            bf[ni][1] = *(const unsigned*)&Ks[n][kk + t4 * 2 + 8];
        }
        #pragma unroll
        for (int mi = 0; mi < 2; ++mi)
            #pragma unroll
            for (int ni = 0; ni < 8; ++ni)
                mma16816(acc[mi][ni], a[mi], bf[ni]);
    }

    #pragma unroll
    for (int ni = 0; ni < 8; ++ni) {
        int col = t0 + warp_n * 64 + ni * 8 + t4 * 2;
        float p0 = (float)amask[bidx * SEQ + col];
        float p1 = (float)amask[bidx * SEQ + col + 1];
        float pm0 = (1.0f - p0) * MASKV;
        float pm1 = (1.0f - p1) * MASKV;
        #pragma unroll
        for (int mi = 0; mi < 2; ++mi) {
            #pragma unroll
            for (int rr = 0; rr < 2; ++rr) {
                int row = s0 + warp_m * 32 + mi * 16 + g + rr * 8;
                float v0 = acc[mi][ni][rr * 2 + 0] * p0 - pm0 - ((col     < row) ? MASKV : 0.f);
                float v1 = acc[mi][ni][rr * 2 + 1] * p1 - pm1 - ((col + 1 < row) ? MASKV : 0.f);
                float2 o;
                o.x = v0 * 0.125f;
                o.y = v1 * 0.125f;
                *(float2*)(out + ((size_t)bh * SEQ + row) * SEQ + col) = o;
            }
        }
    }
}

extern "C" void kernel_launch(void* const* d_in, const int* in_sizes, int n_in,
                              void* d_out, int out_size) {
    (void)in_sizes; (void)n_in; (void)out_size;
    const float* enc  = (const float*)d_in[0];
    const int*   am   = (const int*)d_in[2];
    const float* W    = (const float*)d_in[3];
    const float* bias = (const float*)d_in[4];
    float* out = (float*)d_out;

    __nv_bfloat16* encb; cudaGetSymbolAddress((void**)&encb, g_encb);
    __nv_bfloat16* Wt;   cudaGetSymbolAddress((void**)&Wt,   g_Wt);

    prep_enc<<<1536, 256>>>(enc, encb);
    prep_w<<<dim3(HID / 64, NQK / 64), 256>>>(W, Wt);

    dim3 g1(64, NUM_TAGS);
    gemm1_rope<<<g1, 256>>>(bias);

    dim3 g2(4, 4, BATCH * NUM_TAGS);
    gemm2_mask<<<g2, 256>>>(am, out);
}

// round 4
// speedup vs baseline: 1.2420x; 1.0836x over previous
#include <cuda_runtime.h>
#include <cuda_bf16.h>
#include <cstdint>

#define NUM_TAGS 9
#define DDIM 64
#define HID 768
#define SEQ 512
#define BATCH 16
#define NQK (NUM_TAGS * 2 * DDIM)   /* 1152 */
#define MASKV 1e12f

// Scratch
__device__ __nv_bfloat16 g_Q[(size_t)BATCH * NUM_TAGS * SEQ * DDIM];
__device__ __nv_bfloat16 g_K[(size_t)BATCH * NUM_TAGS * SEQ * DDIM];
__device__ __nv_bfloat16 g_encb[(size_t)BATCH * SEQ * HID];      // enc in bf16
__device__ __nv_bfloat16 g_Wt[(size_t)NQK * HID];                // W^T bf16 [n][k]
__device__ float2 g_rope[SEQ * 32];                              // (sin,cos) per (s,pair)

__device__ __forceinline__ uint32_t smem_u32(const void* p) {
    uint32_t a;
    asm("{ .reg .u64 t; cvta.to.shared.u64 t, %1; cvt.u32.u64 %0, t; }" : "=r"(a) : "l"(p));
    return a;
}
__device__ __forceinline__ void cpasync16s(uint32_t saddr, const void* g) {
    asm volatile("cp.async.cg.shared.global [%0], [%1], 16;\n" :: "r"(saddr), "l"(g));
}
#define CP_COMMIT() asm volatile("cp.async.commit_group;\n")
#define SW128(o) ((o) ^ (((o) >> 3) & 0x70))

__device__ __forceinline__ void mma16816(float* c, const unsigned* a, const unsigned* b) {
    asm volatile(
        "mma.sync.aligned.m16n8k16.row.col.f32.bf16.bf16.f32 "
        "{%0,%1,%2,%3}, {%4,%5,%6,%7}, {%8,%9}, {%0,%1,%2,%3};\n"
        : "+f"(c[0]), "+f"(c[1]), "+f"(c[2]), "+f"(c[3])
        : "r"(a[0]), "r"(a[1]), "r"(a[2]), "r"(a[3]), "r"(b[0]), "r"(b[1]));
}
__device__ __forceinline__ void ldsm_x4(uint32_t addr, uint32_t* r) {
    asm volatile("ldmatrix.sync.aligned.m8n8.x4.shared.b16 {%0,%1,%2,%3}, [%4];"
        : "=r"(r[0]), "=r"(r[1]), "=r"(r[2]), "=r"(r[3]) : "r"(addr));
}

// ===================== Prep kernels =====================
__global__ __launch_bounds__(256) void prep_enc(const float* __restrict__ enc,
                                                __nv_bfloat16* __restrict__ dst) {
    const int NV = BATCH * SEQ * HID / 4;
    const int stride = gridDim.x * blockDim.x;
    for (int i = blockIdx.x * blockDim.x + threadIdx.x; i < NV; i += stride) {
        float4 v = *(const float4*)(enc + (size_t)i * 4);
        __nv_bfloat162 lo = __floats2bfloat162_rn(v.x, v.y);
        __nv_bfloat162 hi = __floats2bfloat162_rn(v.z, v.w);
        uint2 o = { *(unsigned*)&lo, *(unsigned*)&hi };
        *(uint2*)(dst + (size_t)i * 4) = o;
    }
}

__global__ __launch_bounds__(256) void prep_w(const float* __restrict__ W,
                                              __nv_bfloat16* __restrict__ Wt) {
    __shared__ __nv_bfloat16 t[64][72];
    const int kb = blockIdx.x * 64, nb = blockIdx.y * 64;
    const int tid = threadIdx.x;
    #pragma unroll
    for (int it = 0; it < 4; ++it) {
        int idx = tid + it * 256;
        int r = idx >> 4, c4 = (idx & 15) * 4;
        float4 v = *(const float4*)(W + (size_t)(kb + r) * NQK + nb + c4);
        t[c4 + 0][r] = __float2bfloat16_rn(v.x);
        t[c4 + 1][r] = __float2bfloat16_rn(v.y);
        t[c4 + 2][r] = __float2bfloat16_rn(v.z);
        t[c4 + 3][r] = __float2bfloat16_rn(v.w);
    }
    __syncthreads();
    #pragma unroll
    for (int it = 0; it < 4; ++it) {
        int idx = tid + it * 256;
        int r = idx >> 4, c4 = (idx & 15) * 4;
        *(uint2*)(Wt + (size_t)(nb + r) * HID + kb + c4) = *(uint2*)&t[r][c4];
    }
}

__global__ __launch_bounds__(256) void prep_rope(float2* __restrict__ rope) {
    int i = blockIdx.x * blockDim.x + threadIdx.x;
    if (i >= SEQ * 32) return;
    int s = i >> 5, p = i & 31;
    const float LN1E4_OVER_32 = 0.28782313662425572f;
    float inv = expf(-(float)p * LN1E4_OVER_32);
    float sv, cv;
    sincosf((float)s * inv, &sv, &cv);
    rope[i] = make_float2(sv, cv);
}

// ===================== Kernel A: GEMM1 + bias + RoPE (ldmatrix HMMA) ==========
// CTA tile 128(M) x 128(N = one tag). 8 warps = 2(M) x 4(N); warp tile 64x32.
// K-tile 64 (128B rows, SW128), 2-stage cp.async.
#define G1_KT 64
#define G1_NT (HID / G1_KT)          /* 12 */
#define G1_ASZ (128 * 128)           /* 16KB */
#define G1_STAGE (2 * G1_ASZ)        /* 32KB: A then B */
#define G1_DYN (2 * G1_STAGE + 256)

__global__ __launch_bounds__(256) void gemm1_rope(const float* __restrict__ bias)
{
    extern __shared__ char dyn_raw[];
    const uint32_t dsm = (smem_u32(dyn_raw) + 127) & ~127u;
    __shared__ float s_bias[128];

    const int tid  = threadIdx.x;
    const int lane = tid & 31, wid = tid >> 5;
    const int warp_m = wid & 1;        // 0..1
    const int warp_n = wid >> 1;       // 0..3
    const int g  = lane >> 2;
    const int t4 = lane & 3;

    const int m0 = blockIdx.x * 128;
    const int tag = blockIdx.y;
    const int n0 = tag * 128;

    if (tid < 128) s_bias[tid] = bias[n0 + tid];

    const __nv_bfloat16* Ag = g_encb + (size_t)m0 * HID;
    const __nv_bfloat16* Bg = g_Wt   + (size_t)n0 * HID;

    float acc[4][4][4];
    #pragma unroll
    for (int mi = 0; mi < 4; ++mi)
        #pragma unroll
        for (int ni = 0; ni < 4; ++ni)
            #pragma unroll
            for (int q = 0; q < 4; ++q) acc[mi][ni][q] = 0.f;

    // cp.async fill: A and B each 128 rows x 8 16B-chunks = 1024 / 256thr = 4 iters
    auto load_tile = [&](int kt, int st) {
        const int k0 = kt * G1_KT;
        const uint32_t abase = dsm + st * G1_STAGE;
        const uint32_t bbase = abase + G1_ASZ;
        #pragma unroll
        for (int i = 0; i < 4; ++i) {
            int idx = tid + i * 256;
            int r = idx >> 3, c = idx & 7;                 // chunk c: 16B
            uint32_t off = (uint32_t)(r * 128 + c * 16);
            cpasync16s(abase + SW128(off), Ag + (size_t)r * HID + k0 + c * 8);
        }
        #pragma unroll
        for (int i = 0; i < 4; ++i) {
            int idx = tid + i * 256;
            int r = idx >> 3, c = idx & 7;
            uint32_t off = (uint32_t)(r * 128 + c * 16);
            cpasync16s(bbase + SW128(off), Bg + (size_t)r * HID + k0 + c * 8);
        }
    };

    load_tile(0, 0); CP_COMMIT();
    load_tile(1, 1); CP_COMMIT();

    // lane-constant pieces of ldmatrix addressing
    const uint32_t aK = ((lane >> 4) << 3) * 2;            // A: k-half per lane (bytes)
    const uint32_t bK = (((lane >> 3) & 1) << 3) * 2;      // B: k-half per lane (bytes)

    for (int kt = 0; kt < G1_NT; ++kt) {
        const int st = kt & 1;
        if (kt + 1 < G1_NT) asm volatile("cp.async.wait_group 1;\n" ::: "memory");
        else                asm volatile("cp.async.wait_group 0;\n" ::: "memory");
        __syncthreads();

        const uint32_t abase = dsm + st * G1_STAGE;
        const uint32_t bbase = abase + G1_ASZ;

        uint32_t arb[4], axv[4];                           // per-mi row base / xor
        #pragma unroll
        for (int mi = 0; mi < 4; ++mi) {
            int r = warp_m * 64 + mi * 16 + (lane & 15);
            arb[mi] = abase + r * 128;
            axv[mi] = (r & 7) << 4;
        }
        uint32_t brb[2], bxv[2];                           // per-nj (16 n rows each)
        #pragma unroll
        for (int nj = 0; nj < 2; ++nj) {
            int n = warp_n * 32 + nj * 16 + ((lane >> 4) << 3) + (lane & 7);
            brb[nj] = bbase + n * 128;
            bxv[nj] = (n & 7) << 4;
        }

        #pragma unroll
        for (int kk2 = 0; kk2 < 128; kk2 += 32) {          // kk in bytes: 4 steps of k=16
            uint32_t a[4][4], b[2][4];
            #pragma unroll
            for (int mi = 0; mi < 4; ++mi)
                ldsm_x4(arb[mi] + ((kk2 + aK) ^ axv[mi]), a[mi]);
            #pragma unroll
            for (int nj = 0; nj < 2; ++nj)
                ldsm_x4(brb[nj] + ((kk2 + bK) ^ bxv[nj]), b[nj]);
            #pragma unroll
            for (int mi = 0; mi < 4; ++mi) {
                #pragma unroll
                for (int ni = 0; ni < 4; ++ni)
                    mma16816(acc[mi][ni], a[mi], &b[ni >> 1][(ni & 1) * 2]);
            }
        }
        __syncthreads();
        if (kt + 2 < G1_NT) { load_tile(kt + 2, st); CP_COMMIT(); }
    }

    // ---- Epilogue: bias + RoPE -> bf16 Q/K ----
    #pragma unroll
    for (int ni = 0; ni < 4; ++ni) {
        const int col = warp_n * 32 + ni * 8 + t4 * 2;     // 0..127 within tag
        const bool isq = col < 64;
        const int dcol = col & 63;
        const float b0 = s_bias[col], b1 = s_bias[col + 1];
        __nv_bfloat16* dstbase = isq ? g_Q : g_K;
        #pragma unroll
        for (int mi = 0; mi < 4; ++mi) {
            #pragma unroll
            for (int rr = 0; rr < 2; ++rr) {
                const int m = m0 + warp_m * 64 + mi * 16 + g + rr * 8;
                const int bb = m >> 9, s = m & 511;
                float2 sc = g_rope[s * 32 + (dcol >> 1)];
                float v0 = acc[mi][ni][rr * 2 + 0] + b0;
                float v1 = acc[mi][ni][rr * 2 + 1] + b1;
                float y0 = v0 * sc.y - v1 * sc.x;
                float y1 = v1 * sc.y + v0 * sc.x;
                size_t off = (((size_t)(bb * NUM_TAGS + tag) * SEQ + s) * DDIM + dcol);
                *(__nv_bfloat162*)(dstbase + off) = __floats2bfloat162_rn(y0, y1);
            }
        }
    }
}

// ===================== Kernel B: QK^T + mask + scale =====================
__global__ __launch_bounds__(256) void gemm2_mask(
    const int* __restrict__ amask, float* __restrict__ out)
{
    const int tt = blockIdx.x;
    const int st = blockIdx.y;
    const int bh = blockIdx.z;
    const int bidx = bh / NUM_TAGS;
    const int t0 = tt * 128, s0 = st * 128;
    const int tid = threadIdx.x;

    float* outrow0 = out + ((size_t)bh * SEQ + s0) * SEQ;

    if (t0 < s0) {
        #pragma unroll
        for (int it = 0; it < 16; ++it) {
            int idx = tid + it * 256;
            int r = idx >> 5, c4 = (idx & 31) * 4;
            int4 mv = *(const int4*)(amask + bidx * SEQ + t0 + c4);
            float4 o;
            o.x = ((float)mv.x - 2.0f) * 1.25e11f;
            o.y = ((float)mv.y - 2.0f) * 1.25e11f;
            o.z = ((float)mv.z - 2.0f) * 1.25e11f;
            o.w = ((float)mv.w - 2.0f) * 1.25e11f;
            *(float4*)(outrow0 + (size_t)r * SEQ + t0 + c4) = o;
        }
        return;
    }

    __shared__ __align__(16) __nv_bfloat16 Qs[128][72];
    __shared__ __align__(16) __nv_bfloat16 Ks[128][72];

    const __nv_bfloat16* Qg = g_Q + ((size_t)bh * SEQ + s0) * DDIM;
    const __nv_bfloat16* Kg = g_K + ((size_t)bh * SEQ + t0) * DDIM;
    #pragma unroll
    for (int it = 0; it < 4; ++it) {
        int idx = tid + it * 256;
        int r = idx >> 3, c8 = (idx & 7) * 8;
        *(uint4*)&Qs[r][c8] = *(const uint4*)(Qg + (size_t)r * DDIM + c8);
        *(uint4*)&Ks[r][c8] = *(const uint4*)(Kg + (size_t)r * DDIM + c8);
    }
    __syncthreads();

    const int lane = tid & 31, wid = tid >> 5;
    const int warp_m = wid & 3, warp_n = wid >> 2;
    const int g = lane >> 2, t4 = lane & 3;

    float acc[2][8][4];
    #pragma unroll
    for (int mi = 0; mi < 2; ++mi)
        #pragma unroll
        for (int ni = 0; ni < 8; ++ni)
            #pragma unroll
            for (int q = 0; q < 4; ++q) acc[mi][ni][q] = 0.f;

    #pragma unroll
    for (int kk = 0; kk < 64; kk += 16) {
        unsigned a[2][4], bf[8][2];
        #pragma unroll
        for (int mi = 0; mi < 2; ++mi) {
            int r = warp_m * 32 + mi * 16 + g;
            a[mi][0] = *(const unsigned*)&Qs[r][kk + t4 * 2];
            a[mi][1] = *(const unsigned*)&Qs[r + 8][kk + t4 * 2];
            a[mi][2] = *(const unsigned*)&Qs[r][kk + t4 * 2 + 8];
            a[mi][3] = *(const unsigned*)&Qs[r + 8][kk + t4 * 2 + 8];
        }
        #pragma unroll
        for (int ni = 0; ni < 8; ++ni) {
            int n = warp_n * 64 + ni * 8 + g;
            bf[ni][0] = *(const unsigned*)&Ks[n][kk + t4 * 2];
            bf[ni][1] = *(const unsigned*)&Ks[n][kk + t4 * 2 + 8];
        }
        #pragma unroll
        for (int mi = 0; mi < 2; ++mi)
            #pragma unroll
            for (int ni = 0; ni < 8; ++ni)
                mma16816(acc[mi][ni], a[mi], bf[ni]);
    }

    #pragma unroll
    for (int ni = 0; ni < 8; ++ni) {
        int col = t0 + warp_n * 64 + ni * 8 + t4 * 2;
        float p0 = (float)amask[bidx * SEQ + col];
        float p1 = (float)amask[bidx * SEQ + col + 1];
        float pm0 = (1.0f - p0) * MASKV;
        float pm1 = (1.0f - p1) * MASKV;
        #pragma unroll
        for (int mi = 0; mi < 2; ++mi) {
            #pragma unroll
            for (int rr = 0; rr < 2; ++rr) {
                int row = s0 + warp_m * 32 + mi * 16 + g + rr * 8;
                float v0 = acc[mi][ni][rr * 2 + 0] * p0 - pm0 - ((col     < row) ? MASKV : 0.f);
                float v1 = acc[mi][ni][rr * 2 + 1] * p1 - pm1 - ((col + 1 < row) ? MASKV : 0.f);
                float2 o;
                o.x = v0 * 0.125f;
                o.y = v1 * 0.125f;
                *(float2*)(out + ((size_t)bh * SEQ + row) * SEQ + col) = o;
            }
        }
    }
}

extern "C" void kernel_launch(void* const* d_in, const int* in_sizes, int n_in,
                              void* d_out, int out_size) {
    (void)in_sizes; (void)n_in; (void)out_size;
    const float* enc  = (const float*)d_in[0];
    const int*   am   = (const int*)d_in[2];
    const float* W    = (const float*)d_in[3];
    const float* bias = (const float*)d_in[4];
    float* out = (float*)d_out;

    __nv_bfloat16* encb; cudaGetSymbolAddress((void**)&encb, g_encb);
    __nv_bfloat16* Wt;   cudaGetSymbolAddress((void**)&Wt,   g_Wt);
    float2* rope;        cudaGetSymbolAddress((void**)&rope, g_rope);

    cudaFuncSetAttribute(gemm1_rope, cudaFuncAttributeMaxDynamicSharedMemorySize, G1_DYN);

    prep_enc<<<1536, 256>>>(enc, encb);
    prep_w<<<dim3(HID / 64, NQK / 64), 256>>>(W, Wt);
    prep_rope<<<(SEQ * 32 + 255) / 256, 256>>>(rope);

    dim3 g1(64, NUM_TAGS);
    gemm1_rope<<<g1, 256, G1_DYN>>>(bias);

    dim3 g2(4, 4, BATCH * NUM_TAGS);
    gemm2_mask<<<g2, 256>>>(am, out);
}